// round 13
// baseline (speedup 1.0000x reference)
#include <cuda_runtime.h>
#include <cstdint>

#define Bc 4
#define Tc 12
#define Nc 128
#define Hc 64
#define Pc 14
#define G4 256
#define WSTR 44            // bf16x2 words per row (padded, conflict-free frags)

// ---------------- scratch ----------------
__device__ float g_beta [Bc*Nc*Pc];
__device__ float g_gamma[Bc*Nc*Pc];
__device__ float g_clg  [Bc*Nc*Pc*Nc];     // [(b*128+i)*14+p][j]
__device__ float g_cs   [Bc*Pc*Nc*Nc];     // [(b*14+p)*128+i][j] softmaxed, dense
__device__ uint32_t g_Wx [G4*WSTR];
__device__ uint32_t g_WxB[G4*WSTR];
__device__ uint32_t g_WxG[G4*WSTR];

// ---------------- helpers ----------------
__device__ __forceinline__ float sigf(float x){ return __fdividef(1.0f, 1.0f + __expf(-x)); }
__device__ __forceinline__ float tanha(float x){
    float r; asm("tanh.approx.f32 %0, %1;" : "=f"(r) : "f"(x)); return r;
}
__device__ __forceinline__ float sig2(float x){ return fmaf(tanha(0.5f*x), 0.5f, 0.5f); }
__device__ __forceinline__ uint32_t pk(float lo, float hi){
    uint32_t r; asm("cvt.rn.bf16x2.f32 %0, %1, %2;" : "=r"(r) : "f"(hi), "f"(lo)); return r;
}
__device__ __forceinline__ float bflo(uint32_t w){ return __uint_as_float(w << 16); }
__device__ __forceinline__ float bfhi(uint32_t w){ return __uint_as_float(w & 0xffff0000u); }
__device__ __forceinline__ void mma16(float& d0, float& d1, float& d2, float& d3,
                                      uint32_t a0, uint32_t a1, uint32_t a2, uint32_t a3,
                                      uint32_t b0, uint32_t b1){
    asm volatile("mma.sync.aligned.m16n8k16.row.col.f32.bf16.bf16.f32 "
        "{%0,%1,%2,%3}, {%4,%5,%6,%7}, {%8,%9}, {%0,%1,%2,%3};"
        : "+f"(d0), "+f"(d1), "+f"(d2), "+f"(d3)
        : "r"(a0), "r"(a1), "r"(a2), "r"(a3), "r"(b0), "r"(b1));
}

// ---------------- kernel 0: build ext weight tiles (packed bf16x2) ------------
__device__ __forceinline__ float valE(int n, int k, const float* cWhh, const float* cWih, const float* cb){
    if (k < 64) return cWhh[n*64 + k];
    if (k < 67) return cWih[n*6 + (k - 64)];
    if (k < 70) return cWih[n*6 + 3 + (k - 67)];
    if (k == 70) return cb[n];
    return 0.f;
}
__device__ __forceinline__ float valN(int n, int k, const float* Whh, const float* Wih, const float* bb){
    if (k < 64) return Whh[n*64 + k];
    if (k < 67) return Wih[n*3 + (k - 64)];
    if (k == 67) return bb[n];
    return 0.f;
}
__global__ void prep_wx_kernel(const float* __restrict__ cWhh, const float* __restrict__ cWih,
                               const float* __restrict__ cb,
                               const float* __restrict__ bWhh, const float* __restrict__ bWih,
                               const float* __restrict__ bb,
                               const float* __restrict__ gWhh, const float* __restrict__ gWih,
                               const float* __restrict__ gb) {
    int idx = blockIdx.x*256 + threadIdx.x;
    if (idx >= G4*WSTR) return;
    int n = idx / WSTR, wi = idx % WSTR;
    int k0 = 2*wi, k1 = 2*wi + 1;
    g_Wx [idx] = pk(valE(n, k0, cWhh, cWih, cb), valE(n, k1, cWhh, cWih, cb));
    g_WxB[idx] = pk(valN(n, k0, bWhh, bWih, bb), valN(n, k1, bWhh, bWih, bb));
    g_WxG[idx] = pk(valN(n, k0, gWhh, gWih, gb), valN(n, k1, gWhh, gWih, gb));
}

// ---------------- kernel 1: unified LSTM via mma.sync bf16, double-buffered A -
// smem words: B 11264, A0 2816, A1 2816, Xi 48, Xj 3072 -> 20016 f = 80064 B
#define SW_B   0
#define SW_A0  11264
#define SW_A1  14080
#define SF_XI  16896
#define SF_XJ  16944
#define SMF_TOT 20016

__global__ void __launch_bounds__(256, 2)
lstm_mma_kernel(const float* __restrict__ xs,
                const float* __restrict__ cfW, const float* __restrict__ cfb,
                const float* __restrict__ bfW, const float* __restrict__ bfb,
                const float* __restrict__ gfW, const float* __restrict__ gfb) {
    extern __shared__ float sm[];
    uint32_t* BW  = (uint32_t*)sm + SW_B;
    uint32_t* AB[2] = { (uint32_t*)sm + SW_A0, (uint32_t*)sm + SW_A1 };
    float* Xi = sm + SF_XI;
    float* Xj = sm + SF_XJ;
    int tid = threadIdx.x, w = tid >> 5, lane = tid & 31;
    int bx = blockIdx.x;
    bool isEdge = bx < 1024;
    int b = 0, i = 0, j0 = 0, blk = 0, net = 0;
    const uint32_t* Bg;
    if (isEdge) {
        j0 = (bx & 1)*64; i = (bx >> 1) & 127; b = bx >> 8;
        Bg = g_Wx;
    } else {
        int nb = bx - 1024; net = nb >> 3; blk = nb & 7;
        Bg = net ? g_WxG : g_WxB;
    }

    {   // copy weights
        const uint4* src = (const uint4*)Bg;
        uint4* dst = (uint4*)BW;
        for (int idx = tid; idx < 2816; idx += 256) dst[idx] = src[idx];
    }
    // stage x (f32)
    if (isEdge) {
        if (tid < 36) {
            int t = tid/3, q = tid%3;
            Xi[t*4 + q] = xs[(((size_t)(b*Tc + t))*Nc + i)*3 + q];
        }
        for (int idx = tid; idx < 2304; idx += 256) {
            int t = idx/192, r = idx%192, e = r/3, q = r%3;
            Xj[(t*64 + e)*4 + q] = xs[(((size_t)(b*Tc + t))*Nc + j0 + e)*3 + q];
        }
    } else {
        for (int idx = tid; idx < 2304; idx += 256) {
            int t = idx/192, r = idx%192, e = r/3, q = r%3;
            int s = blk*64 + e, bb_ = s >> 7, nn = s & 127;
            Xj[(t*64 + e)*4 + q] = xs[(((size_t)(bb_*Tc + t))*Nc + nn)*3 + q];
        }
    }
    __syncthreads();
    // init ext words (32..43) in BOTH buffers; t=0 values into buf0
    if (tid < 64) {
#pragma unroll
        for (int bu = 0; bu < 2; ++bu) {
            uint32_t* ar = AB[bu] + tid*WSTR;
#pragma unroll
            for (int q = 32; q < WSTR; ++q) ar[q] = 0u;
            if (isEdge) ar[35] = pk(1.0f, 0.f);
        }
        uint32_t* a0 = AB[0] + tid*WSTR;
        const float* xj = Xj + tid*4;
        if (isEdge) {
            a0[32] = pk(Xi[0], Xi[1]);
            a0[33] = pk(Xi[2], xj[0]);
            a0[34] = pk(xj[1], xj[2]);
        } else {
            a0[32] = pk(xj[0], xj[1]);
            a0[33] = pk(xj[2], 1.0f);
        }
    }
    __syncthreads();

    int r0 = lane >> 2, c0 = lane & 3;

    float d[4][4][4];
    float cst[16];
#pragma unroll
    for (int q = 0; q < 16; ++q) cst[q] = 0.f;

    for (int t = 0; t < Tc; ++t) {
        const uint32_t* AW = AB[t & 1];
        uint32_t* AN = AB[(t + 1) & 1];
#pragma unroll
        for (int mt = 0; mt < 4; ++mt)
#pragma unroll
        for (int g = 0; g < 4; ++g)
#pragma unroll
        for (int q = 0; q < 4; ++q) d[mt][g][q] = 0.f;

        for (int kt = (t ? 0 : 4); kt < 5; ++kt) {
            int base = kt*8 + c0;
            uint32_t a[4][4];
#pragma unroll
            for (int mt = 0; mt < 4; ++mt) {
                int rr = mt*16 + r0;
                a[mt][0] = AW[rr*WSTR + base];
                a[mt][1] = AW[(rr+8)*WSTR + base];
                a[mt][2] = AW[rr*WSTR + base + 4];
                a[mt][3] = AW[(rr+8)*WSTR + base + 4];
            }
#pragma unroll
            for (int g = 0; g < 4; ++g) {
                int n0 = g*64 + w*8 + r0;
                uint32_t b0 = BW[n0*WSTR + base];
                uint32_t b1 = BW[n0*WSTR + base + 4];
#pragma unroll
                for (int mt = 0; mt < 4; ++mt)
                    mma16(d[mt][g][0], d[mt][g][1], d[mt][g][2], d[mt][g][3],
                          a[mt][0], a[mt][1], a[mt][2], a[mt][3], b0, b1);
            }
        }
        // no barrier: all writes go to the other buffer
        bool last = (t == Tc - 1);
#pragma unroll
        for (int mt = 0; mt < 4; ++mt)
#pragma unroll
        for (int rr = 0; rr < 2; ++rr) {
            float h2[2];
#pragma unroll
            for (int cc = 0; cc < 2; ++cc) {
                int di = rr*2 + cc;
                float iv = sig2 (d[mt][0][di]);
                float fv = sig2 (d[mt][1][di]);
                float gv = tanha(d[mt][2][di]);
                float ov = sig2 (d[mt][3][di]);
                int ci = mt*4 + rr*2 + cc;
                float cs = fv*cst[ci] + iv*gv;
                cst[ci] = cs;
                h2[cc] = ov*tanha(cs);
            }
            int edge = mt*16 + r0 + rr*8;
            AN[edge*WSTR + w*4 + c0] = pk(h2[0], h2[1]);
        }
        if (!last && tid < 64) {
            uint32_t* ar = AN + tid*WSTR;
            const float* xj = Xj + ((t+1)*64 + tid)*4;
            if (isEdge) {
                const float* xi = Xi + (t+1)*4;
                ar[32] = pk(xi[0], xi[1]);
                ar[33] = pk(xi[2], xj[0]);
                ar[34] = pk(xj[1], xj[2]);
            } else {
                ar[32] = pk(xj[0], xj[1]);
                ar[33] = pk(xj[2], 1.0f);
            }
        }
        __syncthreads();
    }

    // FC + sigmoid: h of t=11 lives in AB[0] words 0..31
    const uint32_t* AH = AB[0];
    const float* fW = isEdge ? cfW : (net ? gfW : bfW);
    const float* fb = isEdge ? cfb : (net ? gfb : bfb);
    if (lane < Pc) {
        float a[8];
#pragma unroll
        for (int e = 0; e < 8; ++e) a[e] = fb[lane];
        for (int wi = 0; wi < 32; ++wi) {
            float w0 = __ldg(&fW[lane*Hc + 2*wi]);
            float w1 = __ldg(&fW[lane*Hc + 2*wi + 1]);
#pragma unroll
            for (int e = 0; e < 8; ++e) {
                uint32_t hw = AH[(w*8 + e)*WSTR + wi];
                a[e] += w0*bflo(hw) + w1*bfhi(hw);
            }
        }
#pragma unroll
        for (int e = 0; e < 8; ++e) {
            float v = sigf(a[e]);
            int row = w*8 + e;
            if (isEdge) {
                g_clg[((size_t)((b*Nc + i)*Pc + lane))*Nc + (j0 + row)] = v;
            } else {
                int s = blk*64 + row;
                (net ? g_gamma : g_beta)[s*Pc + lane] = v;
            }
        }
    }
}

// ---------------- kernel 2: softmax over j + write epi + dense cs -------------
__global__ void softmax_kernel(float* __restrict__ out) {
    int row  = blockIdx.x*4 + (threadIdx.x >> 5);
    int lane = threadIdx.x & 31;
    const float* src = g_clg + (size_t)row*Nc;
    float v[4]; float s = 0.f;
#pragma unroll
    for (int q = 0; q < 4; ++q) { v[q] = __expf(src[lane + 32*q]); s += v[q]; }
#pragma unroll
    for (int off = 16; off; off >>= 1) s += __shfl_xor_sync(0xffffffffu, s, off);
    float inv = __fdividef(1.0f, s);
    int bi = row / Pc, p = row % Pc;
    int b = bi >> 7, i = bi & 127;
    float* e = out + 7168 + ((size_t)((b*Pc + p)*Nc + i))*130;
    float* cs = g_cs + ((size_t)((b*Pc + p)*Nc + i))*Nc;
    if (lane == 0) { e[0] = g_beta[row]; e[1] = g_gamma[row]; }
#pragma unroll
    for (int q = 0; q < 4; ++q) {
        float nv = v[q]*inv;
        e[2 + lane + 32*q]  = nv;
        cs[lane + 32*q]     = nv;
    }
}

// ---------------- kernel 3: SIR scan — double-buffered Ish, 1 barrier/step ----
__global__ void __launch_bounds__(512, 1)
sir_kernel(const float* __restrict__ x, float* __restrict__ out) {
    __shared__ float Ish[2*Nc];        // double-buffered I
    __shared__ float Bgs[2*1792];
    int b = blockIdx.x;
    int tid = threadIdx.x;
    int i = tid >> 2, q = tid & 3;

    for (int idx = tid; idx < 1792; idx += 512) {
        Bgs[idx]        = g_beta [b*1792 + idx];
        Bgs[1792 + idx] = g_gamma[b*1792 + idx];
    }
    // all q lanes carry the chain state
    const float* xp = x + (((size_t)(b*Tc + (Tc-1))*Nc) + i)*3;
    float S = xp[0], I = xp[1], R = xp[2];
    if (q == 0) Ish[i] = I;
    __syncthreads();

    const float4* crow = (const float4*)(g_cs + ((size_t)b*Pc*Nc + i)*Nc) + q*8;
    float4 cur[8];
#pragma unroll
    for (int u = 0; u < 8; ++u) cur[u] = crow[u];

    for (int p = 0; p < Pc; ++p) {
        float4 nxt[8];
        if (p + 1 < Pc) {
            const float4* nr = crow + (size_t)(p+1)*(Nc*Nc/4);
#pragma unroll
            for (int u = 0; u < 8; ++u) nxt[u] = nr[u];
        }
        float acc = 0.f;
        const float* Iq = Ish + (p & 1)*Nc + q*32;
#pragma unroll
        for (int u = 0; u < 8; ++u) {
            acc += cur[u].x*Iq[u*4+0];
            acc += cur[u].y*Iq[u*4+1];
            acc += cur[u].z*Iq[u*4+2];
            acc += cur[u].w*Iq[u*4+3];
        }
        acc += __shfl_xor_sync(0xffffffffu, acc, 1);
        acc += __shfl_xor_sync(0xffffffffu, acc, 2);

        // chain computed by all 4 q lanes redundantly
        float beta = Bgs[i*Pc + p], gamma = Bgs[1792 + i*Pc + p];
        float Ntot = fmaxf(S + I + R, 1e-8f);
        float dS = -beta*S/Ntot*acc;
        float dI = -dS - gamma*I;
        float dR = gamma*I;
        float St = fmaxf(S + dS, 0.f);
        float It = fmaxf(I + dI, 0.f);
        float Rt = fmaxf(R + dR, 0.f);
        float sc = Ntot / fmaxf(St + It + Rt, 1e-8f);
        float Inew = fmaxf(-dS, 0.f);
        St *= sc; It *= sc; Rt *= sc;
        size_t idx = (size_t)(b*Pc + p)*Nc + i;
        if (q == 0) out[idx] = It;                               // o1
        else if (q == 1) {
            float* o3 = out + 7168 + 931840 + idx*3;             // o3
            o3[0] = St; o3[1] = It; o3[2] = Rt;
        }
        else if (q == 2) out[7168 + 931840 + 21504 + idx] = Inew;// o4
        else Ish[((p + 1) & 1)*Nc + i] = It;                     // next-step I (other buffer)
        S = St; I = It; R = Rt;
        __syncthreads();
#pragma unroll
        for (int u = 0; u < 8; ++u) cur[u] = nxt[u];
    }
}

extern "C" void kernel_launch(void* const* d_in, const int* in_sizes, int n_in,
                              void* d_out, int out_size) {
    const float* x_s  = (const float*)d_in[0];
    const float* x    = (const float*)d_in[1];
    const float* bWih = (const float*)d_in[2];
    const float* bWhh = (const float*)d_in[3];
    const float* bb   = (const float*)d_in[4];
    const float* bfW  = (const float*)d_in[5];
    const float* bfb  = (const float*)d_in[6];
    const float* gWih = (const float*)d_in[7];
    const float* gWhh = (const float*)d_in[8];
    const float* gb   = (const float*)d_in[9];
    const float* gfW  = (const float*)d_in[10];
    const float* gfb  = (const float*)d_in[11];
    const float* cWih = (const float*)d_in[12];
    const float* cWhh = (const float*)d_in[13];
    const float* cb   = (const float*)d_in[14];
    const float* cfW  = (const float*)d_in[15];
    const float* cfb  = (const float*)d_in[16];
    float* out = (float*)d_out;

    static bool attr_done = false;
    if (!attr_done) {
        cudaFuncSetAttribute(lstm_mma_kernel, cudaFuncAttributeMaxDynamicSharedMemorySize, SMF_TOT*4);
        attr_done = true;
    }

    prep_wx_kernel<<<44, 256>>>(cWhh, cWih, cb, bWhh, bWih, bb, gWhh, gWih, gb);
    lstm_mma_kernel<<<1040, 256, SMF_TOT*4>>>(x_s, cfW, cfb, bfW, bfb, gfW, gfb);
    softmax_kernel<<<1792, 128>>>(out);
    sir_kernel<<<Bc, 512>>>(x, out);
}

// round 14
// speedup vs baseline: 1.1705x; 1.1705x over previous
#include <cuda_runtime.h>
#include <cstdint>

#define Bc 4
#define Tc 12
#define Nc 128
#define Hc 64
#define Pc 14
#define G4 256
#define WSTR 44            // bf16x2 words per row (padded, conflict-free frags)

// ---------------- scratch ----------------
__device__ float g_beta [Bc*Nc*Pc];
__device__ float g_gamma[Bc*Nc*Pc];
__device__ float g_clg  [Bc*Nc*Pc*Nc];     // [(b*128+i)*14+p][j]
__device__ float g_cs   [Bc*Pc*Nc*Nc];     // [(b*14+p)*128+i][j] softmaxed, dense
__device__ uint32_t g_Wx [G4*WSTR];
__device__ uint32_t g_WxB[G4*WSTR];
__device__ uint32_t g_WxG[G4*WSTR];

// ---------------- helpers ----------------
__device__ __forceinline__ float sigf(float x){ return __fdividef(1.0f, 1.0f + __expf(-x)); }
__device__ __forceinline__ float tanha(float x){
    float r; asm("tanh.approx.f32 %0, %1;" : "=f"(r) : "f"(x)); return r;
}
__device__ __forceinline__ float sig2(float x){ return fmaf(tanha(0.5f*x), 0.5f, 0.5f); }
__device__ __forceinline__ uint32_t pk(float lo, float hi){
    uint32_t r; asm("cvt.rn.bf16x2.f32 %0, %1, %2;" : "=r"(r) : "f"(hi), "f"(lo)); return r;
}
__device__ __forceinline__ float bflo(uint32_t w){ return __uint_as_float(w << 16); }
__device__ __forceinline__ float bfhi(uint32_t w){ return __uint_as_float(w & 0xffff0000u); }
__device__ __forceinline__ void mma16(float& d0, float& d1, float& d2, float& d3,
                                      uint32_t a0, uint32_t a1, uint32_t a2, uint32_t a3,
                                      uint32_t b0, uint32_t b1){
    asm volatile("mma.sync.aligned.m16n8k16.row.col.f32.bf16.bf16.f32 "
        "{%0,%1,%2,%3}, {%4,%5,%6,%7}, {%8,%9}, {%0,%1,%2,%3};"
        : "+f"(d0), "+f"(d1), "+f"(d2), "+f"(d3)
        : "r"(a0), "r"(a1), "r"(a2), "r"(a3), "r"(b0), "r"(b1));
}
__device__ __forceinline__ void ldsm4(uint32_t* r, uint32_t addr){
    asm volatile("ldmatrix.sync.aligned.m8n8.x4.shared.b16 {%0,%1,%2,%3}, [%4];"
        : "=r"(r[0]), "=r"(r[1]), "=r"(r[2]), "=r"(r[3]) : "r"(addr));
}
__device__ __forceinline__ void ldsm2(uint32_t& r0, uint32_t& r1, uint32_t addr){
    asm volatile("ldmatrix.sync.aligned.m8n8.x2.shared.b16 {%0,%1}, [%2];"
        : "=r"(r0), "=r"(r1) : "r"(addr));
}
__device__ __forceinline__ uint32_t smem_u32(const void* p){
    uint32_t a; asm("{ .reg .u64 t; cvta.to.shared.u64 t, %1; cvt.u32.u64 %0, t; }" : "=r"(a) : "l"(p));
    return a;
}

// ---------------- kernel 0: build ext weight tiles (packed bf16x2) ------------
__device__ __forceinline__ float valE(int n, int k, const float* cWhh, const float* cWih, const float* cb){
    if (k < 64) return cWhh[n*64 + k];
    if (k < 67) return cWih[n*6 + (k - 64)];
    if (k < 70) return cWih[n*6 + 3 + (k - 67)];
    if (k == 70) return cb[n];
    return 0.f;
}
__device__ __forceinline__ float valN(int n, int k, const float* Whh, const float* Wih, const float* bb){
    if (k < 64) return Whh[n*64 + k];
    if (k < 67) return Wih[n*3 + (k - 64)];
    if (k == 67) return bb[n];
    return 0.f;
}
__global__ void prep_wx_kernel(const float* __restrict__ cWhh, const float* __restrict__ cWih,
                               const float* __restrict__ cb,
                               const float* __restrict__ bWhh, const float* __restrict__ bWih,
                               const float* __restrict__ bb,
                               const float* __restrict__ gWhh, const float* __restrict__ gWih,
                               const float* __restrict__ gb) {
    int idx = blockIdx.x*256 + threadIdx.x;
    if (idx >= G4*WSTR) return;
    int n = idx / WSTR, wi = idx % WSTR;
    int k0 = 2*wi, k1 = 2*wi + 1;
    g_Wx [idx] = pk(valE(n, k0, cWhh, cWih, cb), valE(n, k1, cWhh, cWih, cb));
    g_WxB[idx] = pk(valN(n, k0, bWhh, bWih, bb), valN(n, k1, bWhh, bWih, bb));
    g_WxG[idx] = pk(valN(n, k0, gWhh, gWih, gb), valN(n, k1, gWhh, gWih, gb));
}

// ---------------- kernel 1: unified LSTM via mma.sync bf16 + ldmatrix ---------
// smem words: B 11264, A 2816, Xi 48, Xj 3072 -> 17200 f = 68800 B
#define SW_B 0
#define SW_A 11264
#define SF_XI 14080
#define SF_XJ 14128
#define SMF_TOT 17200

#define MMA_KT(kt) do {                                                        \
    uint32_t a[4][4];                                                          \
    ldsm4(a[0], aA0 + (kt)*32);                                                \
    ldsm4(a[1], aA1 + (kt)*32);                                                \
    ldsm4(a[2], aA2 + (kt)*32);                                                \
    ldsm4(a[3], aA3 + (kt)*32);                                                \
    uint32_t b0, b1;                                                           \
    ldsm2(b0, b1, aB0 + (kt)*32);                                              \
    mma16(d[0][0][0],d[0][0][1],d[0][0][2],d[0][0][3], a[0][0],a[0][1],a[0][2],a[0][3], b0,b1); \
    mma16(d[1][0][0],d[1][0][1],d[1][0][2],d[1][0][3], a[1][0],a[1][1],a[1][2],a[1][3], b0,b1); \
    mma16(d[2][0][0],d[2][0][1],d[2][0][2],d[2][0][3], a[2][0],a[2][1],a[2][2],a[2][3], b0,b1); \
    mma16(d[3][0][0],d[3][0][1],d[3][0][2],d[3][0][3], a[3][0],a[3][1],a[3][2],a[3][3], b0,b1); \
    ldsm2(b0, b1, aB1 + (kt)*32);                                              \
    mma16(d[0][1][0],d[0][1][1],d[0][1][2],d[0][1][3], a[0][0],a[0][1],a[0][2],a[0][3], b0,b1); \
    mma16(d[1][1][0],d[1][1][1],d[1][1][2],d[1][1][3], a[1][0],a[1][1],a[1][2],a[1][3], b0,b1); \
    mma16(d[2][1][0],d[2][1][1],d[2][1][2],d[2][1][3], a[2][0],a[2][1],a[2][2],a[2][3], b0,b1); \
    mma16(d[3][1][0],d[3][1][1],d[3][1][2],d[3][1][3], a[3][0],a[3][1],a[3][2],a[3][3], b0,b1); \
    ldsm2(b0, b1, aB2 + (kt)*32);                                              \
    mma16(d[0][2][0],d[0][2][1],d[0][2][2],d[0][2][3], a[0][0],a[0][1],a[0][2],a[0][3], b0,b1); \
    mma16(d[1][2][0],d[1][2][1],d[1][2][2],d[1][2][3], a[1][0],a[1][1],a[1][2],a[1][3], b0,b1); \
    mma16(d[2][2][0],d[2][2][1],d[2][2][2],d[2][2][3], a[2][0],a[2][1],a[2][2],a[2][3], b0,b1); \
    mma16(d[3][2][0],d[3][2][1],d[3][2][2],d[3][2][3], a[3][0],a[3][1],a[3][2],a[3][3], b0,b1); \
    ldsm2(b0, b1, aB3 + (kt)*32);                                              \
    mma16(d[0][3][0],d[0][3][1],d[0][3][2],d[0][3][3], a[0][0],a[0][1],a[0][2],a[0][3], b0,b1); \
    mma16(d[1][3][0],d[1][3][1],d[1][3][2],d[1][3][3], a[1][0],a[1][1],a[1][2],a[1][3], b0,b1); \
    mma16(d[2][3][0],d[2][3][1],d[2][3][2],d[2][3][3], a[2][0],a[2][1],a[2][2],a[2][3], b0,b1); \
    mma16(d[3][3][0],d[3][3][1],d[3][3][2],d[3][3][3], a[3][0],a[3][1],a[3][2],a[3][3], b0,b1); \
} while (0)

__global__ void __launch_bounds__(256, 2)
lstm_mma_kernel(const float* __restrict__ xs,
                const float* __restrict__ cfW, const float* __restrict__ cfb,
                const float* __restrict__ bfW, const float* __restrict__ bfb,
                const float* __restrict__ gfW, const float* __restrict__ gfb) {
    extern __shared__ float sm[];
    uint32_t* BW = (uint32_t*)sm + SW_B;
    uint32_t* AW = (uint32_t*)sm + SW_A;
    float* Xi = sm + SF_XI;
    float* Xj = sm + SF_XJ;
    int tid = threadIdx.x, w = tid >> 5, lane = tid & 31;
    int bx = blockIdx.x;
    bool isEdge = bx < 1024;
    int b = 0, i = 0, j0 = 0, blk = 0, net = 0;
    const uint32_t* Bg;
    if (isEdge) {
        j0 = (bx & 1)*64; i = (bx >> 1) & 127; b = bx >> 8;
        Bg = g_Wx;
    } else {
        int nb = bx - 1024; net = nb >> 3; blk = nb & 7;
        Bg = net ? g_WxG : g_WxB;
    }

    {   // copy weights (packed)
        const uint4* src = (const uint4*)Bg;
        uint4* dst = (uint4*)BW;
        for (int idx = tid; idx < 2816; idx += 256) dst[idx] = src[idx];
    }
    // stage x (f32)
    if (isEdge) {
        if (tid < 36) {
            int t = tid/3, q = tid%3;
            Xi[t*4 + q] = xs[(((size_t)(b*Tc + t))*Nc + i)*3 + q];
        }
        for (int idx = tid; idx < 2304; idx += 256) {
            int t = idx/192, r = idx%192, e = r/3, q = r%3;
            Xj[(t*64 + e)*4 + q] = xs[(((size_t)(b*Tc + t))*Nc + j0 + e)*3 + q];
        }
    } else {
        for (int idx = tid; idx < 2304; idx += 256) {
            int t = idx/192, r = idx%192, e = r/3, q = r%3;
            int s = blk*64 + e, bb_ = s >> 7, nn = s & 127;
            Xj[(t*64 + e)*4 + q] = xs[(((size_t)(bb_*Tc + t))*Nc + nn)*3 + q];
        }
    }
    __syncthreads();
    // init A ext words for t=0 (words 32..43)
    if (tid < 64) {
        uint32_t* ar = AW + tid*WSTR;
#pragma unroll
        for (int q = 34; q < WSTR; ++q) ar[q] = 0u;
        if (isEdge) {
            const float* xj = Xj + tid*4;
            ar[32] = pk(Xi[0], Xi[1]);
            ar[33] = pk(Xi[2], xj[0]);
            ar[34] = pk(xj[1], xj[2]);
            ar[35] = pk(1.0f, 0.f);
        } else {
            const float* xj = Xj + tid*4;
            ar[32] = pk(xj[0], xj[1]);
            ar[33] = pk(xj[2], 1.0f);
        }
    }
    __syncthreads();

    int r0 = lane >> 2, c0 = lane & 3;

    // ldmatrix lane addresses (bytes)
    int la7 = lane & 7, la8 = (lane >> 3) & 1, la16 = (lane >> 4) & 1;
    uint32_t baseA = smem_u32(AW), baseB = smem_u32(BW);
    uint32_t aA0 = baseA + ((0*16 + la7 + la8*8)*WSTR + la16*4)*4;
    uint32_t aA1 = baseA + ((1*16 + la7 + la8*8)*WSTR + la16*4)*4;
    uint32_t aA2 = baseA + ((2*16 + la7 + la8*8)*WSTR + la16*4)*4;
    uint32_t aA3 = baseA + ((3*16 + la7 + la8*8)*WSTR + la16*4)*4;
    uint32_t aB0 = baseB + ((0*64 + w*8 + la7)*WSTR + la8*4)*4;
    uint32_t aB1 = baseB + ((1*64 + w*8 + la7)*WSTR + la8*4)*4;
    uint32_t aB2 = baseB + ((2*64 + w*8 + la7)*WSTR + la8*4)*4;
    uint32_t aB3 = baseB + ((3*64 + w*8 + la7)*WSTR + la8*4)*4;

    float d[4][4][4];
    float cst[16];
#pragma unroll
    for (int q = 0; q < 16; ++q) cst[q] = 0.f;

    for (int t = 0; t < Tc; ++t) {
#pragma unroll
        for (int mt = 0; mt < 4; ++mt)
#pragma unroll
        for (int g = 0; g < 4; ++g)
#pragma unroll
        for (int q = 0; q < 4; ++q) d[mt][g][q] = 0.f;

        if (t == 0) {
            MMA_KT(4);
        } else {
#pragma unroll
            for (int kt = 0; kt < 5; ++kt) MMA_KT(kt);
        }
        __syncthreads();
        bool last = (t == Tc - 1);
#pragma unroll
        for (int mt = 0; mt < 4; ++mt)
#pragma unroll
        for (int rr = 0; rr < 2; ++rr) {
            float h2[2];
#pragma unroll
            for (int cc = 0; cc < 2; ++cc) {
                int di = rr*2 + cc;
                float iv = sig2 (d[mt][0][di]);
                float fv = sig2 (d[mt][1][di]);
                float gv = tanha(d[mt][2][di]);
                float ov = sig2 (d[mt][3][di]);
                int ci = mt*4 + rr*2 + cc;
                float cs = fv*cst[ci] + iv*gv;
                cst[ci] = cs;
                h2[cc] = ov*tanha(cs);
            }
            int edge = mt*16 + r0 + rr*8;
            AW[edge*WSTR + w*4 + c0] = pk(h2[0], h2[1]);
        }
        if (!last && tid < 64) {
            uint32_t* ar = AW + tid*WSTR;
            const float* xj = Xj + ((t+1)*64 + tid)*4;
            if (isEdge) {
                const float* xi = Xi + (t+1)*4;
                ar[32] = pk(xi[0], xi[1]);
                ar[33] = pk(xi[2], xj[0]);
                ar[34] = pk(xj[1], xj[2]);
            } else {
                ar[32] = pk(xj[0], xj[1]);
                ar[33] = pk(xj[2], 1.0f);
            }
        }
        __syncthreads();
    }

    // FC + sigmoid: warp w -> rows w*8..w*8+7 (h in bf16 words 0..31)
    const float* fW = isEdge ? cfW : (net ? gfW : bfW);
    const float* fb = isEdge ? cfb : (net ? gfb : bfb);
    if (lane < Pc) {
        float a[8];
#pragma unroll
        for (int e = 0; e < 8; ++e) a[e] = fb[lane];
        for (int wi = 0; wi < 32; ++wi) {
            float w0 = __ldg(&fW[lane*Hc + 2*wi]);
            float w1 = __ldg(&fW[lane*Hc + 2*wi + 1]);
#pragma unroll
            for (int e = 0; e < 8; ++e) {
                uint32_t hw = AW[(w*8 + e)*WSTR + wi];
                a[e] += w0*bflo(hw) + w1*bfhi(hw);
            }
        }
#pragma unroll
        for (int e = 0; e < 8; ++e) {
            float v = sigf(a[e]);
            int row = w*8 + e;
            if (isEdge) {
                g_clg[((size_t)((b*Nc + i)*Pc + lane))*Nc + (j0 + row)] = v;
            } else {
                int s = blk*64 + row;
                (net ? g_gamma : g_beta)[s*Pc + lane] = v;
            }
        }
    }
}

// ---------------- kernel 2: softmax over j + write epi + dense cs -------------
__global__ void softmax_kernel(float* __restrict__ out) {
    int row  = blockIdx.x*4 + (threadIdx.x >> 5);
    int lane = threadIdx.x & 31;
    const float* src = g_clg + (size_t)row*Nc;
    float v[4]; float s = 0.f;
#pragma unroll
    for (int q = 0; q < 4; ++q) { v[q] = __expf(src[lane + 32*q]); s += v[q]; }
#pragma unroll
    for (int off = 16; off; off >>= 1) s += __shfl_xor_sync(0xffffffffu, s, off);
    float inv = __fdividef(1.0f, s);
    int bi = row / Pc, p = row % Pc;
    int b = bi >> 7, i = bi & 127;
    float* e = out + 7168 + ((size_t)((b*Pc + p)*Nc + i))*130;
    float* cs = g_cs + ((size_t)((b*Pc + p)*Nc + i))*Nc;
    if (lane == 0) { e[0] = g_beta[row]; e[1] = g_gamma[row]; }
#pragma unroll
    for (int q = 0; q < 4; ++q) {
        float nv = v[q]*inv;
        e[2 + lane + 32*q]  = nv;
        cs[lane + 32*q]     = nv;
    }
}

// ---------------- kernel 3: SIR scan — direct L2 reads, register prefetch -----
__global__ void __launch_bounds__(512, 1)
sir_kernel(const float* __restrict__ x, float* __restrict__ out) {
    __shared__ float Ish[Nc];
    __shared__ float Bgs[2*1792];
    int b = blockIdx.x;
    int tid = threadIdx.x;
    int i = tid >> 2, q = tid & 3;

    for (int idx = tid; idx < 1792; idx += 512) {
        Bgs[idx]        = g_beta [b*1792 + idx];
        Bgs[1792 + idx] = g_gamma[b*1792 + idx];
    }
    float S = 0.f, I = 0.f, R = 0.f;
    if (q == 0) {
        const float* xp = x + (((size_t)(b*Tc + (Tc-1))*Nc) + i)*3;
        S = xp[0]; I = xp[1]; R = xp[2];
        Ish[i] = I;
    }
    __syncthreads();

    const float4* crow = (const float4*)(g_cs + ((size_t)b*Pc*Nc + i)*Nc) + q*8;
    float4 cur[8];
#pragma unroll
    for (int u = 0; u < 8; ++u) cur[u] = crow[u];

    for (int p = 0; p < Pc; ++p) {
        float4 nxt[8];
        if (p + 1 < Pc) {
            const float4* nr = crow + (size_t)(p+1)*(Nc*Nc/4);
#pragma unroll
            for (int u = 0; u < 8; ++u) nxt[u] = nr[u];
        }
        float acc = 0.f;
        const float* Iq = Ish + q*32;
#pragma unroll
        for (int u = 0; u < 8; ++u) {
            acc += cur[u].x*Iq[u*4+0];
            acc += cur[u].y*Iq[u*4+1];
            acc += cur[u].z*Iq[u*4+2];
            acc += cur[u].w*Iq[u*4+3];
        }
        acc += __shfl_xor_sync(0xffffffffu, acc, 1);
        acc += __shfl_xor_sync(0xffffffffu, acc, 2);
        __syncthreads();
        if (q == 0) {
            float beta = Bgs[i*Pc + p], gamma = Bgs[1792 + i*Pc + p];
            float Ntot = fmaxf(S + I + R, 1e-8f);
            float dS = -beta*S/Ntot*acc;
            float dI = -dS - gamma*I;
            float dR = gamma*I;
            float St = fmaxf(S + dS, 0.f);
            float It = fmaxf(I + dI, 0.f);
            float Rt = fmaxf(R + dR, 0.f);
            float sc = Ntot / fmaxf(St + It + Rt, 1e-8f);
            float Inew = fmaxf(-dS, 0.f);
            St *= sc; It *= sc; Rt *= sc;
            size_t idx = (size_t)(b*Pc + p)*Nc + i;
            out[idx] = It;                                      // o1
            float* o3 = out + 7168 + 931840 + idx*3;            // o3
            o3[0] = St; o3[1] = It; o3[2] = Rt;
            out[7168 + 931840 + 21504 + idx] = Inew;            // o4
            S = St; I = It; R = Rt;
            Ish[i] = I;
        }
        __syncthreads();
#pragma unroll
        for (int u = 0; u < 8; ++u) cur[u] = nxt[u];
    }
}

extern "C" void kernel_launch(void* const* d_in, const int* in_sizes, int n_in,
                              void* d_out, int out_size) {
    const float* x_s  = (const float*)d_in[0];
    const float* x    = (const float*)d_in[1];
    const float* bWih = (const float*)d_in[2];
    const float* bWhh = (const float*)d_in[3];
    const float* bb   = (const float*)d_in[4];
    const float* bfW  = (const float*)d_in[5];
    const float* bfb  = (const float*)d_in[6];
    const float* gWih = (const float*)d_in[7];
    const float* gWhh = (const float*)d_in[8];
    const float* gb   = (const float*)d_in[9];
    const float* gfW  = (const float*)d_in[10];
    const float* gfb  = (const float*)d_in[11];
    const float* cWih = (const float*)d_in[12];
    const float* cWhh = (const float*)d_in[13];
    const float* cb   = (const float*)d_in[14];
    const float* cfW  = (const float*)d_in[15];
    const float* cfb  = (const float*)d_in[16];
    float* out = (float*)d_out;

    static bool attr_done = false;
    if (!attr_done) {
        cudaFuncSetAttribute(lstm_mma_kernel, cudaFuncAttributeMaxDynamicSharedMemorySize, SMF_TOT*4);
        attr_done = true;
    }

    prep_wx_kernel<<<44, 256>>>(cWhh, cWih, cb, bWhh, bWih, bb, gWhh, gWih, gb);
    lstm_mma_kernel<<<1040, 256, SMF_TOT*4>>>(x_s, cfW, cfb, bfW, bfb, gfW, gfb);
    softmax_kernel<<<1792, 128>>>(out);
    sir_kernel<<<Bc, 512>>>(x, out);
}